// round 16
// baseline (speedup 1.0000x reference)
#include <cuda_runtime.h>
#include <cuda_fp16.h>

// Problem constants: imgs [8,3,1024,1024] fp32, z [N,2] fp32, out [8,2] fp32
#define NY  1024
#define NX  1024
#define NB  8                // batches (channel-folded)
#define GBLOCK 256           // gather block: 32 points x 8 lanes
#define GPTS   32            // points per block per step
#define GATHER_BLOCKS 888    // 148 SMs * 6 resident = exactly one wave

// Scratch: duplicated-row fp16 image R[y][x][16] = {P[y][x][0:8], P[y+1][x][0:8]}
// 32 MiB, L2-resident. All 4 bilinear taps of a point = 64B contiguous.
__device__ __align__(128) __half g_R[(size_t)NY * NX * 16];
__device__ float g_partial[GATHER_BLOCKS * 16];
__device__ int   g_ticket;

// ---------------------------------------------------------------------------
// Kernel 1: fold  imgs[b*3+c][y][x] --sum_c--> fp16, written twice:
//   R[y][x][0:8]  and  R[y-1][x][8:16]   (R7-proven version: 21.5us, regs 32)
// ---------------------------------------------------------------------------
__global__ void __launch_bounds__(128) fold_kernel(const float* __restrict__ imgs) {
    if (blockIdx.x == 0 && threadIdx.x == 0) g_ticket = 0;   // graph-replay-safe reset

    const int y = blockIdx.x >> 3;
    const int x = ((blockIdx.x & 7) << 7) + threadIdx.x;

    float s[NB];
    #pragma unroll
    for (int b = 0; b < NB; b++) {
        s[b] = 0.f;
        #pragma unroll
        for (int c = 0; c < 3; c++)
            s[b] += imgs[((size_t)(b * 3 + c) * NY + y) * NX + x];
    }
    __half2 h[4];
    #pragma unroll
    for (int k = 0; k < 4; k++)
        h[k] = __floats2half2_rn(s[2 * k], s[2 * k + 1]);
    const uint4 v = *reinterpret_cast<const uint4*>(h);

    *reinterpret_cast<uint4*>(g_R + ((size_t)y * NX + x) * 16) = v;
    if (y > 0)
        *reinterpret_cast<uint4*>(g_R + ((size_t)(y - 1) * NX + x) * 16 + 8) = v;
}

// ---------------------------------------------------------------------------
// Weight/address computation, 8-lane-per-point view.
// Lane q = (half = q>>2, col = (q>>1)&1, row = q&1); tap sign s as before:
//   c0 = s*(col? wxv:w1x), c1 = s*(row? wyv:w1y), s = +1 iff (q&3) in {1,2}
// 32-bit byte offset (max < 2^30).
// ---------------------------------------------------------------------------
__device__ __forceinline__ void point_setup(
    float2 zz, int row, int col, int half, float s,
    float& c0, float& c1, unsigned& off)
{
    float x0y = zz.x * 1023.0f;
    float x0x = zz.y * 1023.0f;
    bool oob = (x0y < 0.f) | (x0y > 1023.f) | (x0x < 0.f) | (x0x > 1023.f);
    if (oob) { x0y = 0.f; x0x = 0.f; }
    float ygf = floorf(x0y), xgf = floorf(x0x);
    int   yg = min((int)ygf, NY - 2);   // safety clamp (never binds for z in [0,1))
    int   xg = min((int)xgf, NX - 2);
    float fy = ygf - x0y,  fx = xgf - x0x;     // in (-1, 0]
    float valid = oob ? 0.f : 1.f;
    float w1x = (1.f + fx) * valid, wxv = fx * valid;
    float w1y = (1.f + fy) * valid, wyv = fy * valid;
    c0 = s * (col ? wxv : w1x);
    c1 = s * (row ? wyv : w1y);
    off = (unsigned)((((yg << 10) + xg + col) << 5) + (row << 4) + (half << 3));
}

__device__ __forceinline__ void accum(
    uint2 raw, float c0, float c1,
    float* __restrict__ a0, float* __restrict__ a1)
{
    const __half2* hp = reinterpret_cast<const __half2*>(&raw);
    #pragma unroll
    for (int k = 0; k < 2; k++) {
        float2 f = __half22float2(hp[k]);
        a0[2*k]   = fmaf(c0, f.x, a0[2*k]);
        a0[2*k+1] = fmaf(c0, f.y, a0[2*k+1]);
        a1[2*k]   = fmaf(c1, f.x, a1[2*k]);
        a1[2*k+1] = fmaf(c1, f.y, a1[2*k+1]);
    }
}

// ---------------------------------------------------------------------------
// Kernel 2: low-register gather (8 lanes/point, uint2 taps) for 6 blocks/SM
// occupancy. Software-pipelined unroll x4. Same 64B/point footprint as R7
// (1.25 L1tex lines/point). Fused deterministic final reduce in last block.
// ---------------------------------------------------------------------------
__global__ void __launch_bounds__(GBLOCK, 6) gather_kernel(
    const float* __restrict__ z, int n, float* __restrict__ out)
{
    const int t    = threadIdx.x;
    const int q    = t & 7;
    const int row  = q & 1;
    const int col  = (q >> 1) & 1;
    const int half = q >> 2;
    const float s  = (((q & 3) == 1) | ((q & 3) == 2)) ? 1.f : -1.f;
    const int pl   = t >> 3;                        // point slot 0..31
    const int base = blockIdx.x * GPTS + pl;
    const int S    = gridDim.x * GPTS;

    const float2* __restrict__ z2 = reinterpret_cast<const float2*>(z);
    const char*   __restrict__ Rb = reinterpret_cast<const char*>(g_R);

    float a0[4], a1[4];
    #pragma unroll
    for (int k = 0; k < 4; k++) { a0[k] = 0.f; a1[k] = 0.f; }

    int p = base;
    for (; p + 3 * S < n; p += 4 * S) {
        float2 zz[4];
        #pragma unroll
        for (int k = 0; k < 4; k++)
            zz[k] = __ldg(&z2[p + k * S]);          // 4 independent z-loads

        float c0[4], c1[4];
        unsigned off[4];
        uint2 raw[4];
        #pragma unroll
        for (int k = 0; k < 4; k++) {
            point_setup(zz[k], row, col, half, s, c0[k], c1[k], off[k]);
            raw[k] = __ldg(reinterpret_cast<const uint2*>(Rb + off[k]));
        }
        #pragma unroll
        for (int k = 0; k < 4; k++)
            accum(raw[k], c0[k], c1[k], a0, a1);
    }
    for (; p < n; p += S) {
        float2 zz = __ldg(&z2[p]);
        float c0, c1; unsigned off;
        point_setup(zz, row, col, half, s, c0, c1, off);
        uint2 raw = __ldg(reinterpret_cast<const uint2*>(Rb + off));
        accum(raw, c0, c1, a0, a1);
    }

    // Block reduction: 8 floats per thread -> 8KB smem, fixed order.
    __shared__ float sm[GBLOCK * 8];
    #pragma unroll
    for (int k = 0; k < 4; k++) {
        sm[t * 8 + k    ] = a0[k];
        sm[t * 8 + 4 + k] = a1[k];
    }
    __syncthreads();

    if (t < 16) {             // t = b*2 + o ; batch b = half*4 + e
        const int b = t >> 1, o = t & 1;
        const int h = b >> 2, e = b & 3;
        float sum = 0.f;
        #pragma unroll 4
        for (int pp = 0; pp < GPTS; pp++) {
            #pragma unroll
            for (int j = 0; j < 4; j++) {          // the 4 tap-lanes of half h
                int lane_t = pp * 8 + h * 4 + j;
                sum += sm[lane_t * 8 + o * 4 + e];
            }
        }
        g_partial[blockIdx.x * 16 + t] = sum;
    }

    // Fused final reduce: last-arriving block sums all partials (fixed order).
    __shared__ int s_last;
    __threadfence();
    if (t == 0) s_last = (atomicAdd(&g_ticket, 1) == GATHER_BLOCKS - 1);
    __syncthreads();
    if (s_last) {
        __shared__ float red[256];
        const int j = t & 15, g = t >> 4;            // 16 outputs x 16 lanes
        float sum = 0.f;
        for (int i = g; i < GATHER_BLOCKS; i += 16)
            sum += g_partial[i * 16 + j];
        red[t] = sum;
        __syncthreads();
        if (t < 16) {
            float s2 = 0.f;
            #pragma unroll
            for (int g2 = 0; g2 < 16; g2++)
                s2 += red[g2 * 16 + t];
            out[t] = s2;
        }
    }
}

extern "C" void kernel_launch(void* const* d_in, const int* in_sizes, int n_in,
                              void* d_out, int out_size) {
    const float* imgs = (const float*)d_in[0];   // 8*3*1024*1024 fp32
    const float* z    = (const float*)d_in[1];   // N*2 fp32
    const int n_pts   = in_sizes[1] / 2;

    fold_kernel<<<NY * (NX / 128), 128>>>(imgs);
    gather_kernel<<<GATHER_BLOCKS, GBLOCK>>>(z, n_pts, (float*)d_out);
}

// round 17
// speedup vs baseline: 1.0289x; 1.0289x over previous
#include <cuda_runtime.h>
#include <cuda_fp16.h>

// Problem constants: imgs [8,3,1024,1024] fp32, z [N,2] fp32, out [8,2] fp32
#define NY  1024
#define NX  1024
#define NB  8                // batches (channel-folded)
#define GBLOCK 256           // gather block: 32 points x 8 lanes
#define GPTS   32            // points per block per step
#define GATHER_BLOCKS 888    // 148 SMs * 6 resident = exactly one wave

// Scratch: duplicated-row fp16 image R[y][x][16] = {P[y][x][0:8], P[y+1][x][0:8]}
// 32 MiB, L2-resident. All 4 bilinear taps of a point = 64B contiguous.
__device__ __align__(128) __half g_R[(size_t)NY * NX * 16];
__device__ float g_partial[GATHER_BLOCKS * 16];
__device__ int   g_ticket;

// ---------------------------------------------------------------------------
// Kernel 1: fold  imgs[b*3+c][y][x] --sum_c--> fp16, written twice:
//   R[y][x][0:8]  and  R[y-1][x][8:16]   (R7-proven version: 21.5us, regs 32)
// ---------------------------------------------------------------------------
__global__ void __launch_bounds__(128) fold_kernel(const float* __restrict__ imgs) {
    if (blockIdx.x == 0 && threadIdx.x == 0) g_ticket = 0;   // graph-replay-safe reset

    const int y = blockIdx.x >> 3;
    const int x = ((blockIdx.x & 7) << 7) + threadIdx.x;

    float s[NB];
    #pragma unroll
    for (int b = 0; b < NB; b++) {
        s[b] = 0.f;
        #pragma unroll
        for (int c = 0; c < 3; c++)
            s[b] += imgs[((size_t)(b * 3 + c) * NY + y) * NX + x];
    }
    __half2 h[4];
    #pragma unroll
    for (int k = 0; k < 4; k++)
        h[k] = __floats2half2_rn(s[2 * k], s[2 * k + 1]);
    const uint4 v = *reinterpret_cast<const uint4*>(h);

    *reinterpret_cast<uint4*>(g_R + ((size_t)y * NX + x) * 16) = v;
    if (y > 0)
        *reinterpret_cast<uint4*>(g_R + ((size_t)(y - 1) * NX + x) * 16 + 8) = v;
}

// ---------------------------------------------------------------------------
// Weight/address computation, 8-lane-per-point view.
// Lane q = (half = q>>2, col = (q>>1)&1, row = q&1); tap sign s as before:
//   c0 = s*(col? wxv:w1x), c1 = s*(row? wyv:w1y), s = +1 iff (q&3) in {1,2}
// 32-bit byte offset (max < 2^30).
// ---------------------------------------------------------------------------
__device__ __forceinline__ void point_setup(
    float2 zz, int row, int col, int half, float s,
    float& c0, float& c1, unsigned& off)
{
    float x0y = zz.x * 1023.0f;
    float x0x = zz.y * 1023.0f;
    bool oob = (x0y < 0.f) | (x0y > 1023.f) | (x0x < 0.f) | (x0x > 1023.f);
    if (oob) { x0y = 0.f; x0x = 0.f; }
    float ygf = floorf(x0y), xgf = floorf(x0x);
    int   yg = min((int)ygf, NY - 2);   // safety clamp (never binds for z in [0,1))
    int   xg = min((int)xgf, NX - 2);
    float fy = ygf - x0y,  fx = xgf - x0x;     // in (-1, 0]
    float valid = oob ? 0.f : 1.f;
    float w1x = (1.f + fx) * valid, wxv = fx * valid;
    float w1y = (1.f + fy) * valid, wyv = fy * valid;
    c0 = s * (col ? wxv : w1x);
    c1 = s * (row ? wyv : w1y);
    off = (unsigned)((((yg << 10) + xg + col) << 5) + (row << 4) + (half << 3));
}

__device__ __forceinline__ void accum(
    uint2 raw, float c0, float c1,
    float* __restrict__ a0, float* __restrict__ a1)
{
    const __half2* hp = reinterpret_cast<const __half2*>(&raw);
    #pragma unroll
    for (int k = 0; k < 2; k++) {
        float2 f = __half22float2(hp[k]);
        a0[2*k]   = fmaf(c0, f.x, a0[2*k]);
        a0[2*k+1] = fmaf(c0, f.y, a0[2*k+1]);
        a1[2*k]   = fmaf(c1, f.x, a1[2*k]);
        a1[2*k+1] = fmaf(c1, f.y, a1[2*k+1]);
    }
}

// ---------------------------------------------------------------------------
// Kernel 2: low-register gather (8 lanes/point, uint2 taps) for 6 blocks/SM
// occupancy. Software-pipelined unroll x4. Same 64B/point footprint as R7
// (1.25 L1tex lines/point). Fused deterministic final reduce in last block.
// ---------------------------------------------------------------------------
__global__ void __launch_bounds__(GBLOCK, 6) gather_kernel(
    const float* __restrict__ z, int n, float* __restrict__ out)
{
    const int t    = threadIdx.x;
    const int q    = t & 7;
    const int row  = q & 1;
    const int col  = (q >> 1) & 1;
    const int half = q >> 2;
    const float s  = (((q & 3) == 1) | ((q & 3) == 2)) ? 1.f : -1.f;
    const int pl   = t >> 3;                        // point slot 0..31
    const int base = blockIdx.x * GPTS + pl;
    const int S    = gridDim.x * GPTS;

    const float2* __restrict__ z2 = reinterpret_cast<const float2*>(z);
    const char*   __restrict__ Rb = reinterpret_cast<const char*>(g_R);

    float a0[4], a1[4];
    #pragma unroll
    for (int k = 0; k < 4; k++) { a0[k] = 0.f; a1[k] = 0.f; }

    int p = base;
    for (; p + 3 * S < n; p += 4 * S) {
        float2 zz[4];
        #pragma unroll
        for (int k = 0; k < 4; k++)
            zz[k] = __ldg(&z2[p + k * S]);          // 4 independent z-loads

        float c0[4], c1[4];
        unsigned off[4];
        uint2 raw[4];
        #pragma unroll
        for (int k = 0; k < 4; k++) {
            point_setup(zz[k], row, col, half, s, c0[k], c1[k], off[k]);
            raw[k] = __ldg(reinterpret_cast<const uint2*>(Rb + off[k]));
        }
        #pragma unroll
        for (int k = 0; k < 4; k++)
            accum(raw[k], c0[k], c1[k], a0, a1);
    }
    for (; p < n; p += S) {
        float2 zz = __ldg(&z2[p]);
        float c0, c1; unsigned off;
        point_setup(zz, row, col, half, s, c0, c1, off);
        uint2 raw = __ldg(reinterpret_cast<const uint2*>(Rb + off));
        accum(raw, c0, c1, a0, a1);
    }

    // Block reduction: 8 floats per thread -> 8KB smem, fixed order.
    __shared__ float sm[GBLOCK * 8];
    #pragma unroll
    for (int k = 0; k < 4; k++) {
        sm[t * 8 + k    ] = a0[k];
        sm[t * 8 + 4 + k] = a1[k];
    }
    __syncthreads();

    if (t < 16) {             // t = b*2 + o ; batch b = half*4 + e
        const int b = t >> 1, o = t & 1;
        const int h = b >> 2, e = b & 3;
        float sum = 0.f;
        #pragma unroll 4
        for (int pp = 0; pp < GPTS; pp++) {
            #pragma unroll
            for (int j = 0; j < 4; j++) {          // the 4 tap-lanes of half h
                int lane_t = pp * 8 + h * 4 + j;
                sum += sm[lane_t * 8 + o * 4 + e];
            }
        }
        g_partial[blockIdx.x * 16 + t] = sum;
    }

    // Fused final reduce: last-arriving block sums all partials (fixed order).
    __shared__ int s_last;
    __threadfence();
    if (t == 0) s_last = (atomicAdd(&g_ticket, 1) == GATHER_BLOCKS - 1);
    __syncthreads();
    if (s_last) {
        __shared__ float red[256];
        const int j = t & 15, g = t >> 4;            // 16 outputs x 16 lanes
        float sum = 0.f;
        for (int i = g; i < GATHER_BLOCKS; i += 16)
            sum += g_partial[i * 16 + j];
        red[t] = sum;
        __syncthreads();
        if (t < 16) {
            float s2 = 0.f;
            #pragma unroll
            for (int g2 = 0; g2 < 16; g2++)
                s2 += red[g2 * 16 + t];
            out[t] = s2;
        }
    }
}

extern "C" void kernel_launch(void* const* d_in, const int* in_sizes, int n_in,
                              void* d_out, int out_size) {
    const float* imgs = (const float*)d_in[0];   // 8*3*1024*1024 fp32
    const float* z    = (const float*)d_in[1];   // N*2 fp32
    const int n_pts   = in_sizes[1] / 2;

    fold_kernel<<<NY * (NX / 128), 128>>>(imgs);
    gather_kernel<<<GATHER_BLOCKS, GBLOCK>>>(z, n_pts, (float*)d_out);
}